// round 10
// baseline (speedup 1.0000x reference)
#include <cuda_runtime.h>

// MeshFit update_points_feat: per-class exact kNN (K=3) + softmax-weighted
// feature gather. C=4, N=4096, M=4096, D=32. Output (1, C*M, D) float32.
//
// R10: 16x16 grid, WARP-PER-QUERY on cell-sorted queries (zero intra-warp
// query divergence; ring loops fully uniform). Points read straight from
// g_binned via __ldg (L1/L2-resident, 64KB/class) -> smem no longer caps
// occupancy; regs capped at 51 via launch_bounds(256,5) (no spill). Prep is
// ONE 8-block kernel with a parallel scan and smem-only counters (stateless
// across replays). Bin order nondeterminism is harmless: selection is
// lexicographic (d, idx), order-invariant => exact top_k, bit-identical out.

#define CC    4
#define NV    4096
#define MV    4096
#define DF    32
#define GW    16
#define NCELL (GW * GW)
#define CELLW (1.0f / GW)
#define TBQ   256                      // 8 warps = 8 queries per block
#define NBLKQ ((CC * MV) / (TBQ / 32)) // 2048 blocks

__device__ float4 g_binned[CC][NV];           // (x, y, z, idx) in bin order
__device__ int    g_cellStart[CC][NCELL + 1];
__device__ int    g_qorder[CC][MV];           // query ids sorted by cell

__device__ __forceinline__ int clampg(int v) {
    return v < 0 ? 0 : (v > GW - 1 ? GW - 1 : v);
}

__device__ __forceinline__ bool lex_lt(float t, int n, float d, int i) {
    return (t < d) || (t == d && n < i);
}

// Branchless sorted-top-3 insert with lexicographic (d, idx) order.
__device__ __forceinline__ void bl_insert(float t, int n,
                                          float& d0, float& d1, float& d2,
                                          int& i0, int& i1, int& i2)
{
    const bool c0 = lex_lt(t, n, d0, i0);
    const bool c1 = lex_lt(t, n, d1, i1);
    const bool c2 = lex_lt(t, n, d2, i2);
    d2 = c1 ? d1 : (c2 ? t : d2);  i2 = c1 ? i1 : (c2 ? n : i2);
    d1 = c0 ? d0 : (c1 ? t : d1);  i1 = c0 ? i0 : (c1 ? n : i1);
    d0 = c0 ? t  : d0;             i0 = c0 ? n  : i0;
}

// ---- K1: bin points + sort queries (8 blocks, smem-only counters) --------
__global__ void __launch_bounds__(1024, 1)
prep_kernel(const float* __restrict__ verts,
            const float* __restrict__ nverts)
{
    __shared__ int cnt[NCELL];
    __shared__ int sc[NCELL];
    __shared__ int offs[NCELL];
    const int b   = blockIdx.x;
    const int tid = threadIdx.x;
    const bool role = (b >= CC);               // 0: points, 1: queries
    const int  c    = role ? b - CC : b;
    const int  len  = role ? MV : NV;
    const float* src = role ? (nverts + (size_t)c * MV * 3)
                            : (verts + (size_t)c * NV * 3);

    if (tid < NCELL) cnt[tid] = 0;
    __syncthreads();

    for (int n = tid; n < len; n += 1024) {
        const int cx = clampg((int)(src[3 * n + 0] * GW));
        const int cy = clampg((int)(src[3 * n + 1] * GW));
        atomicAdd(&cnt[cy * GW + cx], 1);
    }
    __syncthreads();

    if (tid < NCELL) sc[tid] = cnt[tid];
    __syncthreads();
#pragma unroll
    for (int st = 1; st < NCELL; st <<= 1) {
        int add = 0;
        if (tid < NCELL && tid >= st) add = sc[tid - st];
        __syncthreads();
        if (tid < NCELL) sc[tid] += add;
        __syncthreads();
    }
    if (tid < NCELL) {
        offs[tid] = sc[tid] - cnt[tid];        // exclusive prefix
        if (!role) g_cellStart[c][tid] = offs[tid];
    }
    if (!role && tid == 0) g_cellStart[c][NCELL] = NV;
    __syncthreads();

    for (int n = tid; n < len; n += 1024) {
        const float x = src[3 * n + 0], y = src[3 * n + 1];
        const int cell = clampg((int)(y * GW)) * GW + clampg((int)(x * GW));
        const int slot = atomicAdd(&offs[cell], 1);
        if (role) g_qorder[c][slot] = n;
        else      g_binned[c][slot] = make_float4(x, y, src[3 * n + 2],
                                                  __int_as_float(n));
    }
}

// ---- K2: warp-per-query ring search --------------------------------------
__global__ void __launch_bounds__(TBQ, 5)
query_kernel(const float* __restrict__ feat,
             const float* __restrict__ nverts,
             float* __restrict__ out)
{
    __shared__ int sStart[NCELL + 1];

    const int tid  = threadIdx.x;
    const int warp = tid >> 5;
    const int lane = tid & 31;
    const int c    = blockIdx.x >> 9;          // 512 blocks per class
    const int slot = (blockIdx.x & 511) * (TBQ / 32) + warp;

    for (int i = tid; i < NCELL + 1; i += TBQ) sStart[i] = g_cellStart[c][i];
    __syncthreads();

    const int m = g_qorder[c][slot];
    const float* q = nverts + ((size_t)c * MV + m) * 3;
    const float qx = q[0], qy = q[1], qz = q[2];
    const int cx = clampg((int)(qx * GW));
    const int cy = clampg((int)(qy * GW));
    const float4* __restrict__ pts = g_binned[c];

    float d0 = 3.402823466e38f, d1 = 3.402823466e38f, d2 = 3.402823466e38f;
    int   i0 = 0x7fffffff, i1 = 0x7fffffff, i2 = 0x7fffffff;

#pragma unroll 1
    for (int r = 0; r < GW; ++r) {
        const int y0 = cy - r < 0 ? 0 : cy - r;
        const int y1 = cy + r > GW - 1 ? GW - 1 : cy + r;
        const int x0 = cx - r < 0 ? 0 : cx - r;
        const int x1 = cx + r > GW - 1 ? GW - 1 : cx + r;
#pragma unroll 1
        for (int Y = y0; Y <= y1; ++Y) {
            const bool edge_y = (Y == cy - r) || (Y == cy + r);
#pragma unroll 1
            for (int X = x0; X <= x1; ++X) {
                if (!edge_y && X != cx - r && X != cx + r) continue;
                const int cell = Y * GW + X;
                const int s = sStart[cell], e = sStart[cell + 1];
                for (int p = s + lane; p < e; p += 32) {   // lanes stride
                    const float4 pt = __ldg(&pts[p]);
                    const float dx = qx - pt.x;
                    const float dy = qy - pt.y;
                    const float dz = qz - pt.z;
                    const float t = fmaf(dz, dz, fmaf(dy, dy, dx * dx));
                    bl_insert(t, __float_as_int(pt.w), d0, d1, d2, i0, i1, i2);
                }
            }
        }
        // Stop bound: B = min over 32 lanes of local d2 (>= true d2).
        float B = d2;
#pragma unroll
        for (int off = 1; off < 32; off <<= 1)
            B = fminf(B, __shfl_xor_sync(0xffffffffu, B, off));
        const float sL = (cx - r <= 0)      ? 1e30f : qx - (cx - r) * CELLW;
        const float sR = (cx + r >= GW - 1) ? 1e30f : (cx + r + 1) * CELLW - qx;
        const float sB = (cy - r <= 0)      ? 1e30f : qy - (cy - r) * CELLW;
        const float sT = (cy + r >= GW - 1) ? 1e30f : (cy + r + 1) * CELLW - qy;
        const float dmin = fminf(fminf(sL, sR), fminf(sB, sT));
        if (B * 1.00001f < dmin * dmin) break;             // warp-uniform
    }

    // Butterfly merge across 32 lanes; lex (d, idx) = exact top_k order.
#pragma unroll
    for (int off = 1; off < 32; off <<= 1) {
        const float pd0 = __shfl_xor_sync(0xffffffffu, d0, off);
        const float pd1 = __shfl_xor_sync(0xffffffffu, d1, off);
        const float pd2 = __shfl_xor_sync(0xffffffffu, d2, off);
        const int   pi0 = __shfl_xor_sync(0xffffffffu, i0, off);
        const int   pi1 = __shfl_xor_sync(0xffffffffu, i1, off);
        const int   pi2 = __shfl_xor_sync(0xffffffffu, i2, off);
        bl_insert(pd0, pi0, d0, d1, d2, i0, i1, i2);
        bl_insert(pd1, pi1, d0, d1, d2, i0, i1, i2);
        bl_insert(pd2, pi2, d0, d1, d2, i0, i1, i2);
    }

    // Global column indices + exact merge of constant-1.0 off-block fillers.
    const int base = c * NV;
    int g0 = base + i0, g1 = base + i1, g2 = base + i2;
    const int fbase = (c == 0) ? NV : 0;
#pragma unroll
    for (int k = 0; k < 3; ++k)
        bl_insert(1.0f, fbase + k, d0, d1, d2, g0, g1, g2);

    // softmax(-d), max-subtracted (d0 smallest).
    const float e1 = expf(d0 - d1);
    const float e2 = expf(d0 - d2);
    const float inv = 1.0f / (1.0f + e1 + e2);
    const float w0 = inv, w1 = e1 * inv, w2 = e2 * inv;

    // Gather: lanes 0..23 load row(lane/8) chunk(lane%8), weighted; fold
    // rows with two shfl-down steps; lanes 0..7 store the 8 output chunks.
    const int row   = lane >> 3;
    const int chunk = lane & 7;
    float4 v = make_float4(0.f, 0.f, 0.f, 0.f);
    if (lane < 24) {
        const int   g = (row == 0) ? g0 : (row == 1) ? g1 : g2;
        const float w = (row == 0) ? w0 : (row == 1) ? w1 : w2;
        const float4 f = __ldg(&((const float4*)(feat + (size_t)g * DF))[chunk]);
        v = make_float4(w * f.x, w * f.y, w * f.z, w * f.w);
    }
    v.x += __shfl_down_sync(0xffffffffu, v.x, 16);
    v.y += __shfl_down_sync(0xffffffffu, v.y, 16);
    v.z += __shfl_down_sync(0xffffffffu, v.z, 16);
    v.w += __shfl_down_sync(0xffffffffu, v.w, 16);
    v.x += __shfl_down_sync(0xffffffffu, v.x, 8);
    v.y += __shfl_down_sync(0xffffffffu, v.y, 8);
    v.z += __shfl_down_sync(0xffffffffu, v.z, 8);
    v.w += __shfl_down_sync(0xffffffffu, v.w, 8);
    if (lane < 8)
        ((float4*)(out + ((size_t)c * MV + m) * DF))[chunk] = v;
}

extern "C" void kernel_launch(void* const* d_in, const int* in_sizes, int n_in,
                              void* d_out, int out_size)
{
    const float* feat   = (const float*)d_in[0];  // (1, C*N, D)
    const float* verts  = (const float*)d_in[1];  // (C, N, 3)
    const float* nverts = (const float*)d_in[2];  // (C, M, 3)
    float* out = (float*)d_out;                   // (1, C*M, D)

    prep_kernel<<<2 * CC, 1024>>>(verts, nverts);
    query_kernel<<<NBLKQ, TBQ>>>(feat, nverts, out);
}